// round 13
// baseline (speedup 1.0000x reference)
#include <cuda_runtime.h>
#include <cuda_fp16.h>
#include <math_constants.h>

#define Bc 2
#define Hc 12
#define Nc 2048
#define Dc 128
#define Wc 64
#define TOT_ELEM (Bc*Hc*Nc*Dc)   // 6,291,456

// fp16-staged K and V — device-global scratch (no allocation).
static __device__ __align__(16) __half g_kh[TOT_ELEM];
static __device__ __align__(16) __half g_vh[TOT_ELEM];

// ---------------------------------------------------------------------------
// Pre-pass: convert K and V fp32 -> fp16 (8 elems / thread). HBM-bound (~11us).
// ---------------------------------------------------------------------------
__global__ void __launch_bounds__(256) convert_fp16_kernel(
    const float4* __restrict__ k4, const float4* __restrict__ v4)
{
    const int n8 = TOT_ELEM / 8;
    int i = blockIdx.x * blockDim.x + threadIdx.x;
    if (i >= 2 * n8) return;

    const float4* src;
    uint4* dst;
    if (i < n8) { src = k4; dst = reinterpret_cast<uint4*>(g_kh); }
    else        { src = v4; dst = reinterpret_cast<uint4*>(g_vh); i -= n8; }

    const float4 a = src[2 * i];
    const float4 b = src[2 * i + 1];
    __half2 h0 = __floats2half2_rn(a.x, a.y);
    __half2 h1 = __floats2half2_rn(a.z, a.w);
    __half2 h2 = __floats2half2_rn(b.x, b.y);
    __half2 h3 = __floats2half2_rn(b.z, b.w);
    uint4 o;
    o.x = *reinterpret_cast<unsigned*>(&h0);
    o.y = *reinterpret_cast<unsigned*>(&h1);
    o.z = *reinterpret_cast<unsigned*>(&h2);
    o.w = *reinterpret_cast<unsigned*>(&h3);
    dst[i] = o;
}

// Fold-merge across xor `mask` (2 SEL + SHFL + FADD).
__device__ __forceinline__ float fold(float a, float b, int mask, bool bit)
{
    float send = bit ? a : b;
    float keep = bit ? b : a;
    float recv = __shfl_xor_sync(0xffffffffu, send, mask);
    return keep + recv;
}

// ---------------------------------------------------------------------------
// Fused single-pass kernel (R8 structure): one warp per (b,h,n).
// Constant-shift softmax (scores bounded, exp(s-14) safe -> no max pass).
// K/V gathers use __ldcg (L2-only, no L1 allocate): the ~1MB/bh working set
// mostly misses the 228KB L1 anyway; bypassing kills L1 fill/evict overhead
// on the streaming gather traffic while L2 (63% busy) absorbs the hits.
// Per 16-row group:
//   1. 8 dual-row K gathers, batched (MLP=8)
//   2. HFMA2 partial dots -> late fold tree -> e = expf(s-14)
//   3. 8 dual-row V gathers (reuse column ids from registers) -> FFMA accum
// ---------------------------------------------------------------------------
__global__ void __launch_bounds__(256, 4) sparse_attn_kernel(
    const float* __restrict__ q,
    const int*   __restrict__ col_ids,
    float*       __restrict__ out)
{
    const unsigned FULL = 0xffffffffu;
    const int gwarp = (blockIdx.x * blockDim.x + threadIdx.x) >> 5;
    if (gwarp >= Bc * Hc * Nc) return;
    const int lane    = threadIdx.x & 31;
    const int lanelow = lane & 15;
    const int halfsel = lane >> 4;

    const int n  = gwarp & (Nc - 1);
    const int bh = gwarp >> 11;

    // q for this lane's 8 d-elements, pre-scaled by 1/sqrt(D), as half2.
    const float scale = 0.08838834764831845f;
    const float4* q4 = reinterpret_cast<const float4*>(q) + (size_t)gwarp * (Dc / 4);
    const float4 qa = q4[lanelow * 2];
    const float4 qb = q4[lanelow * 2 + 1];
    __half2 qh[4];
    qh[0] = __floats2half2_rn(qa.x * scale, qa.y * scale);
    qh[1] = __floats2half2_rn(qa.z * scale, qa.w * scale);
    qh[2] = __floats2half2_rn(qb.x * scale, qb.y * scale);
    qh[3] = __floats2half2_rn(qb.z * scale, qb.w * scale);

    const int* cid = col_ids + n * Wc;
    const int c_lo = cid[lane];
    const int c_hi = cid[lane + 32];

    const uint4* kb4 = reinterpret_cast<const uint4*>(g_kh) + (size_t)bh * Nc * 16;
    const uint4* vb4 = reinterpret_cast<const uint4*>(g_vh) + (size_t)bh * Nc * 16;

    const bool bit8 = (lane & 8) != 0;
    const bool bit4 = (lane & 4) != 0;
    const bool bit2 = (lane & 2) != 0;
    const int lane16 = lane & 16;

    float l = 0.0f;
    float acc[8];
    #pragma unroll
    for (int i = 0; i < 8; ++i) acc[i] = 0.0f;

    #pragma unroll
    for (int g = 0; g < 4; ++g) {
        // ---- stage 1: 8 dual-row K gathers (batched, L2-only) ------------
        int   off[8];
        uint4 kr[8];
        #pragma unroll
        for (int j = 0; j < 8; ++j) {
            const int w0  = g * 16 + 2 * j;
            const int src = (w0 & 31) + halfsel;
            const int c   = __shfl_sync(FULL, (g < 2) ? c_lo : c_hi, src);
            off[j] = c * 16 + lanelow;
            kr[j]  = __ldcg(kb4 + off[j]);
        }

        // ---- stage 2: HFMA2 partial dots ----------------------------------
        float p[8];
        #pragma unroll
        for (int j = 0; j < 8; ++j) {
            const __half2 h0 = *reinterpret_cast<const __half2*>(&kr[j].x);
            const __half2 h1 = *reinterpret_cast<const __half2*>(&kr[j].y);
            const __half2 h2 = *reinterpret_cast<const __half2*>(&kr[j].z);
            const __half2 h3 = *reinterpret_cast<const __half2*>(&kr[j].w);
            __half2 a2 = __hmul2(h0, qh[0]);
            a2 = __hfma2(h1, qh[1], a2);
            __half2 b2 = __hmul2(h2, qh[2]);
            b2 = __hfma2(h3, qh[3], b2);
            const __half2 s2 = __hadd2(a2, b2);
            const float2 f = __half22float2(s2);
            p[j] = f.x + f.y;
        }

        // ---- stage 3: fold tree + constant-shift exp ----------------------
        float q0 = fold(p[0], p[1], 8, bit8);
        float q1 = fold(p[2], p[3], 8, bit8);
        float q2 = fold(p[4], p[5], 8, bit8);
        float q3 = fold(p[6], p[7], 8, bit8);
        float r0 = fold(q0, q1, 4, bit4);
        float r1 = fold(q2, q3, 4, bit4);
        float s  = fold(r0, r1, 2, bit2);
        s += __shfl_xor_sync(FULL, s, 1);

        const float eg = __expf(s - 14.0f);
        l += eg;

        // ---- stage 4: 8 dual-row V gathers (L2-only) + accumulate ---------
        #pragma unroll
        for (int j = 0; j < 8; ++j) {
            const int srcw = ((j & 1) << 3) | ((j & 2) << 1) | ((j & 4) >> 1) | lane16;
            const float ew = __shfl_sync(FULL, eg, srcw);
            const uint4 raw = __ldcg(vb4 + off[j]);
            const float2 f0 = __half22float2(*reinterpret_cast<const __half2*>(&raw.x));
            const float2 f1 = __half22float2(*reinterpret_cast<const __half2*>(&raw.y));
            const float2 f2 = __half22float2(*reinterpret_cast<const __half2*>(&raw.z));
            const float2 f3 = __half22float2(*reinterpret_cast<const __half2*>(&raw.w));
            acc[0] = fmaf(ew, f0.x, acc[0]);
            acc[1] = fmaf(ew, f0.y, acc[1]);
            acc[2] = fmaf(ew, f1.x, acc[2]);
            acc[3] = fmaf(ew, f1.y, acc[3]);
            acc[4] = fmaf(ew, f2.x, acc[4]);
            acc[5] = fmaf(ew, f2.y, acc[5]);
            acc[6] = fmaf(ew, f3.x, acc[6]);
            acc[7] = fmaf(ew, f3.y, acc[7]);
        }
    }

    // ---- global weight sum (scores distributed over lane bits 1..4) ------
    l += __shfl_xor_sync(FULL, l, 2);
    l += __shfl_xor_sync(FULL, l, 4);
    l += __shfl_xor_sync(FULL, l, 8);
    l += __shfl_xor_sync(FULL, l, 16);

    // ---- merge even/odd row halves, normalize, store ---------------------
    #pragma unroll
    for (int i = 0; i < 8; ++i)
        acc[i] += __shfl_xor_sync(FULL, acc[i], 16);

    if (lane < 16) {
        const float inv = 1.0f / l;
        float4* o4 = reinterpret_cast<float4*>(out) + (size_t)gwarp * (Dc / 4);
        float4 oa, ob;
        oa.x = acc[0] * inv; oa.y = acc[1] * inv;
        oa.z = acc[2] * inv; oa.w = acc[3] * inv;
        ob.x = acc[4] * inv; ob.y = acc[5] * inv;
        ob.z = acc[6] * inv; ob.w = acc[7] * inv;
        o4[lanelow * 2]     = oa;
        o4[lanelow * 2 + 1] = ob;
    }
}

extern "C" void kernel_launch(void* const* d_in, const int* in_sizes, int n_in,
                              void* d_out, int out_size)
{
    const float* q   = (const float*)d_in[0];
    const float* k   = (const float*)d_in[1];
    const float* v   = (const float*)d_in[2];
    const int*   cid = (const int*)d_in[3];
    float*       out = (float*)d_out;

    {
        const int threads = 256;
        const int work    = 2 * (TOT_ELEM / 8);
        const int blocks  = (work + threads - 1) / threads;
        convert_fp16_kernel<<<blocks, threads>>>(
            reinterpret_cast<const float4*>(k),
            reinterpret_cast<const float4*>(v));
    }
    {
        const int total_warps = Bc * Hc * Nc;
        const int threads     = 256;
        const int blocks      = (total_warps * 32 + threads - 1) / threads;
        sparse_attn_kernel<<<blocks, threads>>>(q, cid, out);
    }
}

// round 14
// speedup vs baseline: 1.0288x; 1.0288x over previous
#include <cuda_runtime.h>
#include <cuda_fp16.h>
#include <math_constants.h>

#define Bc 2
#define Hc 12
#define Nc 2048
#define Dc 128
#define Wc 64
#define TOT_ELEM (Bc*Hc*Nc*Dc)   // 6,291,456

// fp16-staged K and V — device-global scratch (no allocation).
static __device__ __align__(16) __half g_kh[TOT_ELEM];
static __device__ __align__(16) __half g_vh[TOT_ELEM];

// ---------------------------------------------------------------------------
// Pre-pass: convert K and V fp32 -> fp16 (8 elems / thread). HBM-bound (~11us).
// ---------------------------------------------------------------------------
__global__ void __launch_bounds__(256) convert_fp16_kernel(
    const float4* __restrict__ k4, const float4* __restrict__ v4)
{
    const int n8 = TOT_ELEM / 8;
    int i = blockIdx.x * blockDim.x + threadIdx.x;
    if (i >= 2 * n8) return;

    const float4* src;
    uint4* dst;
    if (i < n8) { src = k4; dst = reinterpret_cast<uint4*>(g_kh); }
    else        { src = v4; dst = reinterpret_cast<uint4*>(g_vh); i -= n8; }

    const float4 a = src[2 * i];
    const float4 b = src[2 * i + 1];
    __half2 h0 = __floats2half2_rn(a.x, a.y);
    __half2 h1 = __floats2half2_rn(a.z, a.w);
    __half2 h2 = __floats2half2_rn(b.x, b.y);
    __half2 h3 = __floats2half2_rn(b.z, b.w);
    uint4 o;
    o.x = *reinterpret_cast<unsigned*>(&h0);
    o.y = *reinterpret_cast<unsigned*>(&h1);
    o.z = *reinterpret_cast<unsigned*>(&h2);
    o.w = *reinterpret_cast<unsigned*>(&h3);
    dst[i] = o;
}

// Fold-merge across xor `mask` (2 SEL + SHFL + FADD).
__device__ __forceinline__ float fold(float a, float b, int mask, bool bit)
{
    float send = bit ? a : b;
    float keep = bit ? b : a;
    float recv = __shfl_xor_sync(0xffffffffu, send, mask);
    return keep + recv;
}

// ---------------------------------------------------------------------------
// Fused single-pass kernel: one warp per (b,h,n).
// Constant-shift softmax (scores bounded, exp(s-14) safe -> no max pass).
// Per 16-row group:
//   1. 8 dual-row K gathers, batched (MLP=8)
//   2. HFMA2 partial dots (kr dies)
//   2.5 PREFETCH first 4 V rows (vr[4], 16 regs) -> these cover the
//       fold-tree SHFL chain's ~150-cycle latency bubble
//   3. fold tree + e = expf(s-14)
//   4a. accumulate prefetched V rows 0..3
//   4b. load + accumulate V rows 4..7
// Register budget deliberately kept < 64 (R11 lesson: spills kill overlap).
// ---------------------------------------------------------------------------
__global__ void __launch_bounds__(256, 4) sparse_attn_kernel(
    const float* __restrict__ q,
    const int*   __restrict__ col_ids,
    float*       __restrict__ out)
{
    const unsigned FULL = 0xffffffffu;
    const int gwarp = (blockIdx.x * blockDim.x + threadIdx.x) >> 5;
    if (gwarp >= Bc * Hc * Nc) return;
    const int lane    = threadIdx.x & 31;
    const int lanelow = lane & 15;
    const int halfsel = lane >> 4;

    const int n  = gwarp & (Nc - 1);
    const int bh = gwarp >> 11;

    // q for this lane's 8 d-elements, pre-scaled by 1/sqrt(D), as half2.
    const float scale = 0.08838834764831845f;
    const float4* q4 = reinterpret_cast<const float4*>(q) + (size_t)gwarp * (Dc / 4);
    const float4 qa = q4[lanelow * 2];
    const float4 qb = q4[lanelow * 2 + 1];
    __half2 qh[4];
    qh[0] = __floats2half2_rn(qa.x * scale, qa.y * scale);
    qh[1] = __floats2half2_rn(qa.z * scale, qa.w * scale);
    qh[2] = __floats2half2_rn(qb.x * scale, qb.y * scale);
    qh[3] = __floats2half2_rn(qb.z * scale, qb.w * scale);

    const int* cid = col_ids + n * Wc;
    const int c_lo = cid[lane];
    const int c_hi = cid[lane + 32];

    const uint4* kb4 = reinterpret_cast<const uint4*>(g_kh) + (size_t)bh * Nc * 16;
    const uint4* vb4 = reinterpret_cast<const uint4*>(g_vh) + (size_t)bh * Nc * 16;

    const bool bit8 = (lane & 8) != 0;
    const bool bit4 = (lane & 4) != 0;
    const bool bit2 = (lane & 2) != 0;
    const int lane16 = lane & 16;

    float l = 0.0f;
    float acc[8];
    #pragma unroll
    for (int i = 0; i < 8; ++i) acc[i] = 0.0f;

    #pragma unroll
    for (int g = 0; g < 4; ++g) {
        // ---- stage 1: 8 dual-row K gathers (batched, MLP=8) --------------
        int   off[8];
        uint4 kr[8];
        #pragma unroll
        for (int j = 0; j < 8; ++j) {
            const int w0  = g * 16 + 2 * j;
            const int src = (w0 & 31) + halfsel;
            const int c   = __shfl_sync(FULL, (g < 2) ? c_lo : c_hi, src);
            off[j] = c * 16 + lanelow;
            kr[j]  = kb4[off[j]];
        }

        // ---- stage 2: HFMA2 partial dots (kr dies here) -------------------
        float p[8];
        #pragma unroll
        for (int j = 0; j < 8; ++j) {
            const __half2 h0 = *reinterpret_cast<const __half2*>(&kr[j].x);
            const __half2 h1 = *reinterpret_cast<const __half2*>(&kr[j].y);
            const __half2 h2 = *reinterpret_cast<const __half2*>(&kr[j].z);
            const __half2 h3 = *reinterpret_cast<const __half2*>(&kr[j].w);
            __half2 a2 = __hmul2(h0, qh[0]);
            a2 = __hfma2(h1, qh[1], a2);
            __half2 b2 = __hmul2(h2, qh[2]);
            b2 = __hfma2(h3, qh[3], b2);
            const __half2 s2 = __hadd2(a2, b2);
            const float2 f = __half22float2(s2);
            p[j] = f.x + f.y;
        }

        // ---- stage 2.5: prefetch first 4 V rows (covers fold-tree bubble)
        uint4 vr[4];
        #pragma unroll
        for (int j = 0; j < 4; ++j)
            vr[j] = vb4[off[j]];

        // ---- stage 3: fold tree + constant-shift exp ----------------------
        float q0 = fold(p[0], p[1], 8, bit8);
        float q1 = fold(p[2], p[3], 8, bit8);
        float q2 = fold(p[4], p[5], 8, bit8);
        float q3 = fold(p[6], p[7], 8, bit8);
        float r0 = fold(q0, q1, 4, bit4);
        float r1 = fold(q2, q3, 4, bit4);
        float s  = fold(r0, r1, 2, bit2);
        s += __shfl_xor_sync(FULL, s, 1);

        const float eg = __expf(s - 14.0f);
        l += eg;

        // ---- stage 4a: accumulate prefetched V rows 0..3 ------------------
        #pragma unroll
        for (int j = 0; j < 4; ++j) {
            const int srcw = ((j & 1) << 3) | ((j & 2) << 1) | ((j & 4) >> 1) | lane16;
            const float ew = __shfl_sync(FULL, eg, srcw);
            const float2 f0 = __half22float2(*reinterpret_cast<const __half2*>(&vr[j].x));
            const float2 f1 = __half22float2(*reinterpret_cast<const __half2*>(&vr[j].y));
            const float2 f2 = __half22float2(*reinterpret_cast<const __half2*>(&vr[j].z));
            const float2 f3 = __half22float2(*reinterpret_cast<const __half2*>(&vr[j].w));
            acc[0] = fmaf(ew, f0.x, acc[0]);
            acc[1] = fmaf(ew, f0.y, acc[1]);
            acc[2] = fmaf(ew, f1.x, acc[2]);
            acc[3] = fmaf(ew, f1.y, acc[3]);
            acc[4] = fmaf(ew, f2.x, acc[4]);
            acc[5] = fmaf(ew, f2.y, acc[5]);
            acc[6] = fmaf(ew, f3.x, acc[6]);
            acc[7] = fmaf(ew, f3.y, acc[7]);
        }

        // ---- stage 4b: load + accumulate V rows 4..7 -----------------------
        #pragma unroll
        for (int j = 4; j < 8; ++j) {
            const int srcw = ((j & 1) << 3) | ((j & 2) << 1) | ((j & 4) >> 1) | lane16;
            const float ew = __shfl_sync(FULL, eg, srcw);
            const uint4 raw = vb4[off[j]];
            const float2 f0 = __half22float2(*reinterpret_cast<const __half2*>(&raw.x));
            const float2 f1 = __half22float2(*reinterpret_cast<const __half2*>(&raw.y));
            const float2 f2 = __half22float2(*reinterpret_cast<const __half2*>(&raw.z));
            const float2 f3 = __half22float2(*reinterpret_cast<const __half2*>(&raw.w));
            acc[0] = fmaf(ew, f0.x, acc[0]);
            acc[1] = fmaf(ew, f0.y, acc[1]);
            acc[2] = fmaf(ew, f1.x, acc[2]);
            acc[3] = fmaf(ew, f1.y, acc[3]);
            acc[4] = fmaf(ew, f2.x, acc[4]);
            acc[5] = fmaf(ew, f2.y, acc[5]);
            acc[6] = fmaf(ew, f3.x, acc[6]);
            acc[7] = fmaf(ew, f3.y, acc[7]);
        }
    }

    // ---- global weight sum (scores distributed over lane bits 1..4) ------
    l += __shfl_xor_sync(FULL, l, 2);
    l += __shfl_xor_sync(FULL, l, 4);
    l += __shfl_xor_sync(FULL, l, 8);
    l += __shfl_xor_sync(FULL, l, 16);

    // ---- merge even/odd row halves, normalize, store ---------------------
    #pragma unroll
    for (int i = 0; i < 8; ++i)
        acc[i] += __shfl_xor_sync(FULL, acc[i], 16);

    if (lane < 16) {
        const float inv = 1.0f / l;
        float4* o4 = reinterpret_cast<float4*>(out) + (size_t)gwarp * (Dc / 4);
        float4 oa, ob;
        oa.x = acc[0] * inv; oa.y = acc[1] * inv;
        oa.z = acc[2] * inv; oa.w = acc[3] * inv;
        ob.x = acc[4] * inv; ob.y = acc[5] * inv;
        ob.z = acc[6] * inv; ob.w = acc[7] * inv;
        o4[lanelow * 2]     = oa;
        o4[lanelow * 2 + 1] = ob;
    }
}

extern "C" void kernel_launch(void* const* d_in, const int* in_sizes, int n_in,
                              void* d_out, int out_size)
{
    const float* q   = (const float*)d_in[0];
    const float* k   = (const float*)d_in[1];
    const float* v   = (const float*)d_in[2];
    const int*   cid = (const int*)d_in[3];
    float*       out = (float*)d_out;

    {
        const int threads = 256;
        const int work    = 2 * (TOT_ELEM / 8);
        const int blocks  = (work + threads - 1) / threads;
        convert_fp16_kernel<<<blocks, threads>>>(
            reinterpret_cast<const float4*>(k),
            reinterpret_cast<const float4*>(v));
    }
    {
        const int total_warps = Bc * Hc * Nc;
        const int threads     = 256;
        const int blocks      = (total_warps * 32 + threads - 1) / threads;
        sparse_attn_kernel<<<blocks, threads>>>(q, cid, out);
    }
}